// round 4
// baseline (speedup 1.0000x reference)
#include <cuda_runtime.h>
#include <math.h>

#define BATCH 4
#define SEQ   2048
#define DIMN  1024
#define NH    8
#define HD    128
#define MROWS (BATCH*SEQ)   // 8192

// ---------------- scratch (device globals; no runtime allocation) ----------------
__device__ float g_wgate[(size_t)MROWS*DIMN];          // Wgate
__device__ float g_xy[(size_t)MROWS*DIMN];             // X (per-head proj) then Y (groupnorm out)
__device__ float g_sr[(size_t)MROWS*DIMN];             // Sq (suffix scan) then retention out
__device__ float g_colscale[(size_t)BATCH*NH*SEQ];     // per-column scale

__device__ __forceinline__ float swishf(float x) { return x / (1.0f + expf(-x)); }

// =================================================================================
// Generic 128x128 tile SGEMM: C = epi(A (⊙A2) @ B + bias). M,N mult of 128, K mult of 16.
// =================================================================================
template<bool SWISH, bool AMUL>
__global__ __launch_bounds__(256)
void sgemm128(const float* __restrict__ A, const float* __restrict__ A2,
              const float* __restrict__ Bm, const float* __restrict__ bias,
              float* __restrict__ C, int K, int N)
{
    __shared__ float As[16][132];   // transposed, padded
    __shared__ float Bs[16][128];
    const int tid = threadIdx.x;
    const int tx = tid & 15;
    const int ty = tid >> 4;
    const int rowBase = blockIdx.y * 128;
    const int colBase = blockIdx.x * 128;
    const int aRow = tid >> 2;          // 0..63
    const int aCol = (tid & 3) << 2;    // 0,4,8,12
    const int bRow = tid >> 5;          // 0..7
    const int bCol = (tid & 31) << 2;   // 0..124

    float acc[8][8];
    #pragma unroll
    for (int m = 0; m < 8; ++m)
        #pragma unroll
        for (int n = 0; n < 8; ++n) acc[m][n] = 0.0f;

    for (int k0 = 0; k0 < K; k0 += 16) {
        #pragma unroll
        for (int s2 = 0; s2 < 2; ++s2) {
            int r = aRow + s2 * 64;
            float4 v = *(const float4*)(A + (size_t)(rowBase + r) * K + k0 + aCol);
            if (AMUL) {
                float4 w = *(const float4*)(A2 + (size_t)(rowBase + r) * K + k0 + aCol);
                v.x *= w.x; v.y *= w.y; v.z *= w.z; v.w *= w.w;
            }
            As[aCol + 0][r] = v.x; As[aCol + 1][r] = v.y;
            As[aCol + 2][r] = v.z; As[aCol + 3][r] = v.w;
        }
        #pragma unroll
        for (int s2 = 0; s2 < 2; ++s2) {
            int r = bRow + s2 * 8;
            *(float4*)&Bs[r][bCol] = *(const float4*)(Bm + (size_t)(k0 + r) * N + colBase + bCol);
        }
        __syncthreads();
        #pragma unroll
        for (int k = 0; k < 16; ++k) {
            float ra[8], rb[8];
            *(float4*)&ra[0] = *(float4*)&As[k][ty * 8];
            *(float4*)&ra[4] = *(float4*)&As[k][ty * 8 + 4];
            *(float4*)&rb[0] = *(float4*)&Bs[k][tx * 8];
            *(float4*)&rb[4] = *(float4*)&Bs[k][tx * 8 + 4];
            #pragma unroll
            for (int m = 0; m < 8; ++m)
                #pragma unroll
                for (int n = 0; n < 8; ++n)
                    acc[m][n] = fmaf(ra[m], rb[n], acc[m][n]);
        }
        __syncthreads();
    }

    #pragma unroll
    for (int m = 0; m < 8; ++m) {
        int row = rowBase + ty * 8 + m;
        #pragma unroll
        for (int n = 0; n < 8; n += 4) {
            int col = colBase + tx * 8 + n;
            float4 o;
            o.x = acc[m][n + 0] + bias[col + 0];
            o.y = acc[m][n + 1] + bias[col + 1];
            o.z = acc[m][n + 2] + bias[col + 2];
            o.w = acc[m][n + 3] + bias[col + 3];
            if (SWISH) { o.x = swishf(o.x); o.y = swishf(o.y); o.z = swishf(o.z); o.w = swishf(o.w); }
            *(float4*)(C + (size_t)row * N + col) = o;
        }
    }
}

// =================================================================================
// Per-head projection: X[b,h,s,:] = q[b,s, h*128 : (h+1)*128] @ W_qkv[h]
// =================================================================================
__global__ __launch_bounds__(256)
void proj_kernel(const float* __restrict__ q, const float* __restrict__ Wqkv,
                 float* __restrict__ Xout)
{
    __shared__ float Ast[32][65];    // [k][row]
    __shared__ float Ws[32][128];    // [k][d]
    const int h = blockIdx.y;
    const int row0 = blockIdx.x * 64;
    const int tid = threadIdx.x;
    const int tx = tid & 15, ty = tid >> 4;
    const float* Wh = Wqkv + (size_t)h * HD * HD;

    float acc[4][8];
    #pragma unroll
    for (int m = 0; m < 4; ++m)
        #pragma unroll
        for (int n = 0; n < 8; ++n) acc[m][n] = 0.0f;

    for (int k0 = 0; k0 < HD; k0 += 32) {
        __syncthreads();
        for (int p = tid; p < 512; p += 256) {           // 64 rows x 8 float4
            int r = p >> 3, k4 = (p & 7) << 2;
            float4 v = *(const float4*)(q + (size_t)(row0 + r) * DIMN + h * HD + k0 + k4);
            Ast[k4 + 0][r] = v.x; Ast[k4 + 1][r] = v.y;
            Ast[k4 + 2][r] = v.z; Ast[k4 + 3][r] = v.w;
        }
        for (int p = tid; p < 1024; p += 256) {          // 32 k x 32 float4
            int k = p >> 5, d4 = (p & 31) << 2;
            *(float4*)&Ws[k][d4] = *(const float4*)(Wh + (size_t)(k0 + k) * HD + d4);
        }
        __syncthreads();
        #pragma unroll
        for (int k = 0; k < 32; ++k) {
            float ra[4], rb[8];
            #pragma unroll
            for (int m = 0; m < 4; ++m) ra[m] = Ast[k][ty * 4 + m];
            #pragma unroll
            for (int n = 0; n < 8; ++n) rb[n] = Ws[k][tx + (n << 4)];
            #pragma unroll
            for (int m = 0; m < 4; ++m)
                #pragma unroll
                for (int n = 0; n < 8; ++n)
                    acc[m][n] = fmaf(ra[m], rb[n], acc[m][n]);
        }
    }
    #pragma unroll
    for (int m = 0; m < 4; ++m) {
        int i = row0 + ty * 4 + m;
        int b = i >> 11, s = i & (SEQ - 1);
        float* op = Xout + ((size_t)(b * NH + h) * SEQ + s) * HD;
        #pragma unroll
        for (int n = 0; n < 8; ++n) op[tx + (n << 4)] = acc[m][n];
    }
}

// =================================================================================
// Backward suffix scan: Sq[t] = X[t] + gamma * Sq[t+1]   (per (b,h), per dim)
// =================================================================================
__global__ void scan_kernel(float* __restrict__ Sq, const float* __restrict__ X)
{
    const int bh = blockIdx.x;
    const int h = bh & (NH - 1);
    const float gamma = 1.0f - exp2f(-5.0f - (float)h);
    const float* Xh = X + (size_t)bh * SEQ * HD;
    float* Sh = Sq + (size_t)bh * SEQ * HD;
    const int d = threadIdx.x;
    float sq = 0.0f;
    for (int t = SEQ - 1; t >= 0; --t) {
        sq = fmaf(gamma, sq, Xh[(size_t)t * HD + d]);
        Sh[(size_t)t * HD + d] = sq;
    }
}

// =================================================================================
// colscale[t] = rsqrt(c_t)/sqrt(HD) / max(|col_s[t]|,1),
// col_s[t] = rsqrt(c_t)/sqrt(HD) * dot(X[t], Sq[t]),  c_t = (1-g^(S-t))/(1-g)
// =================================================================================
__global__ __launch_bounds__(256)
void colscale_kernel(float* __restrict__ colscale, const float* __restrict__ X,
                     const float* __restrict__ Sq)
{
    const int bh = blockIdx.x;
    const int h = bh & (NH - 1);
    const float gamma = 1.0f - exp2f(-5.0f - (float)h);
    const float l2g = log2f(gamma);
    const float inv1mg = exp2f(5.0f + (float)h);  // 1/(1-gamma), exact
    const int warp = threadIdx.x >> 5, lane = threadIdx.x & 31;
    const float inv_s = rsqrtf((float)HD);
    #pragma unroll
    for (int i = 0; i < 8; ++i) {
        int t = blockIdx.y * 64 + warp * 8 + i;
        const float* xr = X + ((size_t)bh * SEQ + t) * HD;
        const float* sr = Sq + ((size_t)bh * SEQ + t) * HD;
        float4 xv = *(const float4*)(xr + lane * 4);
        float4 sv = *(const float4*)(sr + lane * 4);
        float dot = xv.x * sv.x + xv.y * sv.y + xv.z * sv.z + xv.w * sv.w;
        #pragma unroll
        for (int o = 16; o; o >>= 1) dot += __shfl_xor_sync(0xffffffffu, dot, o);
        if (lane == 0) {
            float ct = (1.0f - exp2f((float)(SEQ - t) * l2g)) * inv1mg;
            float rs = rsqrtf(ct);
            float colsum = dot * rs * inv_s;
            colscale[(size_t)bh * SEQ + t] = rs * inv_s / fmaxf(fabsf(colsum), 1.0f);
        }
    }
}

// =================================================================================
// Retention: out[s,:] += sum_{t<=s} (X[s]·X[t]) * gamma^(s-t) * colscale[t] * X[t,:]
// 64x64 tiles, triangular key loop, K==V==X (single tile load).
// =================================================================================
#define RET_SMEM ((64*129*2 + 64*65 + 64 + 64) * 4)

__global__ __launch_bounds__(256)
void retention_kernel(float* __restrict__ out, const float* __restrict__ X,
                      const float* __restrict__ colscale)
{
    extern __shared__ float sm[];
    float* Qs   = sm;                      // 64 x 129
    float* KVs  = Qs + 64 * 129;           // 64 x 129
    float* Sw   = KVs + 64 * 129;          // 64 x 65
    float* wcol = Sw + 64 * 65;            // 64
    float* powr = wcol + 64;               // 64

    const int sb = blockIdx.x;
    const int bh = blockIdx.y;
    const int h = bh & (NH - 1);
    const int b = bh >> 3;
    const float gamma = 1.0f - exp2f(-5.0f - (float)h);
    const float l2g = log2f(gamma);
    const float* Xh = X + (size_t)bh * SEQ * HD;
    const float* csb = colscale + (size_t)bh * SEQ;
    const int tid = threadIdx.x;
    const int tx = tid & 15, ty = tid >> 4;
    const int s0 = sb * 64;

    // Q tile
    for (int p = tid; p < 64 * 32; p += 256) {
        int r = p >> 5, k4 = (p & 31) << 2;
        float4 v = *(const float4*)(Xh + (size_t)(s0 + r) * HD + k4);
        Qs[r * 129 + k4] = v.x; Qs[r * 129 + k4 + 1] = v.y;
        Qs[r * 129 + k4 + 2] = v.z; Qs[r * 129 + k4 + 3] = v.w;
    }
    if (tid < 64) powr[tid] = exp2f((float)tid * l2g);  // gamma^i, i=0..63

    float acc[4][8];
    #pragma unroll
    for (int m = 0; m < 4; ++m)
        #pragma unroll
        for (int n = 0; n < 8; ++n) acc[m][n] = 0.0f;

    for (int jb = 0; jb <= sb; ++jb) {
        const int t0 = jb * 64;
        __syncthreads();   // protect KVs/Sw from previous iteration readers
        for (int p = tid; p < 64 * 32; p += 256) {
            int r = p >> 5, k4 = (p & 31) << 2;
            float4 v = *(const float4*)(Xh + (size_t)(t0 + r) * HD + k4);
            KVs[r * 129 + k4] = v.x; KVs[r * 129 + k4 + 1] = v.y;
            KVs[r * 129 + k4 + 2] = v.z; KVs[r * 129 + k4 + 3] = v.w;
        }
        if (tid < 64) {
            // gamma^(s0 - (t0+j)) * colscale[t0+j]; combined with powr[s-s0] => gamma^(s-t)*cs
            wcol[tid] = exp2f((float)(s0 - t0 - tid) * l2g) * csb[t0 + tid];
        }
        __syncthreads();

        // scores: S[i][j] = Q[i]·K[j]
        float sc[4][4];
        #pragma unroll
        for (int m = 0; m < 4; ++m)
            #pragma unroll
            for (int n = 0; n < 4; ++n) sc[m][n] = 0.0f;
        for (int k = 0; k < HD; ++k) {
            float ra[4], rb[4];
            #pragma unroll
            for (int m = 0; m < 4; ++m) ra[m] = Qs[(ty * 4 + m) * 129 + k];
            #pragma unroll
            for (int n = 0; n < 4; ++n) rb[n] = KVs[(tx * 4 + n) * 129 + k];
            #pragma unroll
            for (int m = 0; m < 4; ++m)
                #pragma unroll
                for (int n = 0; n < 4; ++n)
                    sc[m][n] = fmaf(ra[m], rb[n], sc[m][n]);
        }
        // weight + stage to smem
        #pragma unroll
        for (int m = 0; m < 4; ++m) {
            int rl = ty * 4 + m;
            int srow = s0 + rl;
            #pragma unroll
            for (int n = 0; n < 4; ++n) {
                int cl = tx * 4 + n;
                int tcol = t0 + cl;
                float w = (srow >= tcol) ? powr[rl] * wcol[cl] : 0.0f;
                Sw[rl * 65 + cl] = sc[m][n] * w;
            }
        }
        __syncthreads();
        // acc += Sw @ KV   (V == K tile)
        #pragma unroll 4
        for (int j = 0; j < 64; ++j) {
            float sv[4], bv[8];
            #pragma unroll
            for (int m = 0; m < 4; ++m) sv[m] = Sw[(ty * 4 + m) * 65 + j];
            #pragma unroll
            for (int n = 0; n < 8; ++n) bv[n] = KVs[j * 129 + tx + (n << 4)];
            #pragma unroll
            for (int m = 0; m < 4; ++m)
                #pragma unroll
                for (int n = 0; n < 8; ++n)
                    acc[m][n] = fmaf(sv[m], bv[n], acc[m][n]);
        }
    }

    #pragma unroll
    for (int m = 0; m < 4; ++m) {
        int srow = s0 + ty * 4 + m;
        float* op = out + ((size_t)(b * SEQ + srow)) * DIMN + h * HD;
        #pragma unroll
        for (int n = 0; n < 8; ++n) op[tx + (n << 4)] = acc[m][n];
    }
}

// =================================================================================
// GroupNorm: 32 groups of 32 channels, population var, eps=1e-3, + beta
// =================================================================================
__global__ __launch_bounds__(256)
void groupnorm_kernel(float* __restrict__ Y, const float* __restrict__ Xin,
                      const float* __restrict__ beta)
{
    int row = blockIdx.x >> 2;
    int gblk = blockIdx.x & 3;
    int warp = threadIdx.x >> 5, lane = threadIdx.x & 31;
    int c = gblk * 256 + warp * 32 + lane;
    float x = Xin[(size_t)row * DIMN + c];
    float s = x, s2 = x * x;
    #pragma unroll
    for (int o = 16; o; o >>= 1) {
        s  += __shfl_xor_sync(0xffffffffu, s, o);
        s2 += __shfl_xor_sync(0xffffffffu, s2, o);
    }
    float mu = s * (1.0f / 32.0f);
    float var = s2 * (1.0f / 32.0f) - mu * mu;
    float y = (x - mu) * rsqrtf(var + 1e-3f) + beta[c];
    Y[(size_t)row * DIMN + c] = y;
}

// =================================================================================
// Launch
// =================================================================================
extern "C" void kernel_launch(void* const* d_in, const int* in_sizes, int n_in,
                              void* d_out, int out_size)
{
    const float* q    = (const float*)d_in[0];
    // d_in[1] = k, d_in[2] = v : unused by the reference (retention uses q for Q,K,V)
    const float* Wqkv = (const float*)d_in[3];
    const float* Wg   = (const float*)d_in[4];
    const float* bg   = (const float*)d_in[5];
    const float* Wo   = (const float*)d_in[6];
    const float* bo   = (const float*)d_in[7];
    const float* beta = (const float*)d_in[8];
    float* out = (float*)d_out;

    float *wgate, *xy, *sr, *cscale;
    cudaGetSymbolAddress((void**)&wgate, g_wgate);
    cudaGetSymbolAddress((void**)&xy, g_xy);
    cudaGetSymbolAddress((void**)&sr, g_sr);
    cudaGetSymbolAddress((void**)&cscale, g_colscale);

    cudaFuncSetAttribute(retention_kernel, cudaFuncAttributeMaxDynamicSharedMemorySize, RET_SMEM);

    // 1. Wgate = swish(q @ Wg + bg)
    sgemm128<true, false><<<dim3(DIMN / 128, MROWS / 128), 256>>>(q, nullptr, Wg, bg, wgate, DIMN, DIMN);
    // 2. X[b,h,s,:] = q_h @ W_qkv[h]
    proj_kernel<<<dim3(MROWS / 64, NH), 256>>>(q, Wqkv, xy);
    // 3. Sq suffix scan (into g_sr)
    scan_kernel<<<BATCH * NH, HD>>>(sr, xy);
    // 4. per-column scale
    colscale_kernel<<<dim3(BATCH * NH, SEQ / 64), 256>>>(cscale, xy, sr);
    // 5. retention (overwrites g_sr with attention output, interleaved [row, h*128+d])
    retention_kernel<<<dim3(SEQ / 64, BATCH * NH), 256, RET_SMEM>>>(sr, xy, cscale);
    // 6. group norm (writes Y into g_xy; X no longer needed)
    groupnorm_kernel<<<MROWS * 4, 256>>>(xy, sr, beta);
    // 7. out = (Wgate ⊙ Y) @ Wo + bo
    sgemm128<false, true><<<dim3(DIMN / 128, MROWS / 128), 256>>>(wgate, xy, Wo, bo, out, DIMN, DIMN);
}

// round 8
// speedup vs baseline: 2.3652x; 2.3652x over previous
#include <cuda_runtime.h>
#include <math.h>
#include <stdint.h>

#define BATCH 4
#define SEQ   2048
#define DIMN  1024
#define NH    8
#define HD    128
#define MROWS (BATCH*SEQ)   // 8192

// ---------------- scratch (device globals; no runtime allocation) ----------------
__device__ float g_wgate[(size_t)MROWS*DIMN];          // Wgate
__device__ float g_xy[(size_t)MROWS*DIMN];             // X (per-head proj) then Y (groupnorm out)
__device__ float g_sr[(size_t)MROWS*DIMN];             // Sq (suffix scan) then retention out
__device__ float g_colscale[(size_t)BATCH*NH*SEQ];     // per-column scale

__device__ __forceinline__ float swishf(float x) { return x / (1.0f + expf(-x)); }

__device__ __forceinline__ uint32_t f2tf32(float x) {
    uint32_t y;
    asm("cvt.rna.tf32.f32 %0, %1;" : "=r"(y) : "f"(x));
    return y;
}

// D += A*B, m16n8k8 tf32, fp32 accumulate
__device__ __forceinline__ void mma8(float* d, uint32_t a0, uint32_t a1, uint32_t a2, uint32_t a3,
                                     uint32_t b0, uint32_t b1) {
    asm volatile("mma.sync.aligned.m16n8k8.row.col.f32.tf32.tf32.f32 "
                 "{%0,%1,%2,%3},{%4,%5,%6,%7},{%8,%9},{%0,%1,%2,%3};"
                 : "+f"(d[0]), "+f"(d[1]), "+f"(d[2]), "+f"(d[3])
                 : "r"(a0), "r"(a1), "r"(a2), "r"(a3), "r"(b0), "r"(b1));
}

// =================================================================================
// TF32 tensor-core SGEMM: C = epi(A (⊙A2) @ B + bias). 128x128 block, 8 warps.
// Warp tile 32x64. As[m][k] stride 36 (frag banks (4m+k)%32 distinct),
// Bs[k][n] stride 136 (frag banks (8n+k)%32 distinct). K mult of 32.
// =================================================================================
template<bool SWISH, bool AMUL>
__global__ __launch_bounds__(256)
void sgemm_tf32(const float* __restrict__ A, const float* __restrict__ A2,
                const float* __restrict__ Bm, const float* __restrict__ bias,
                float* __restrict__ C, int K, int N)
{
    __shared__ uint32_t As[128 * 36];
    __shared__ uint32_t Bs[32 * 136];
    const int tid = threadIdx.x;
    const int warp = tid >> 5, lane = tid & 31;
    const int wr = warp >> 1, wc = warp & 1;
    const int lr = lane >> 2, lc = lane & 3;
    const int rowBase = blockIdx.y * 128;
    const int colBase = blockIdx.x * 128;

    float acc[2][8][4];
    #pragma unroll
    for (int mt = 0; mt < 2; ++mt)
        #pragma unroll
        for (int nt = 0; nt < 8; ++nt)
            #pragma unroll
            for (int i = 0; i < 4; ++i) acc[mt][nt][i] = 0.0f;

    for (int k0 = 0; k0 < K; k0 += 32) {
        // A tile: 128 rows x 32 k (converted to tf32 at store)
        #pragma unroll
        for (int q4 = 0; q4 < 4; ++q4) {
            int p = tid + q4 * 256;
            int r = p >> 3, kc = (p & 7) << 2;
            float4 v = *(const float4*)(A + (size_t)(rowBase + r) * K + k0 + kc);
            if (AMUL) {
                float4 w = *(const float4*)(A2 + (size_t)(rowBase + r) * K + k0 + kc);
                v.x *= w.x; v.y *= w.y; v.z *= w.z; v.w *= w.w;
            }
            uint32_t* dst = &As[r * 36 + kc];
            dst[0] = f2tf32(v.x); dst[1] = f2tf32(v.y);
            dst[2] = f2tf32(v.z); dst[3] = f2tf32(v.w);
        }
        // B tile: 32 k x 128 n
        #pragma unroll
        for (int q4 = 0; q4 < 4; ++q4) {
            int p = tid + q4 * 256;
            int r = p >> 5, nc = (p & 31) << 2;
            float4 v = *(const float4*)(Bm + (size_t)(k0 + r) * N + colBase + nc);
            uint32_t* dst = &Bs[r * 136 + nc];
            dst[0] = f2tf32(v.x); dst[1] = f2tf32(v.y);
            dst[2] = f2tf32(v.z); dst[3] = f2tf32(v.w);
        }
        __syncthreads();
        #pragma unroll
        for (int k8 = 0; k8 < 4; ++k8) {
            const int kb = k8 * 8;
            uint32_t a[2][4];
            #pragma unroll
            for (int mt = 0; mt < 2; ++mt) {
                int m = wr * 32 + mt * 16;
                a[mt][0] = As[(m + lr) * 36 + kb + lc];
                a[mt][1] = As[(m + lr + 8) * 36 + kb + lc];
                a[mt][2] = As[(m + lr) * 36 + kb + lc + 4];
                a[mt][3] = As[(m + lr + 8) * 36 + kb + lc + 4];
            }
            #pragma unroll
            for (int nt = 0; nt < 8; ++nt) {
                int n = wc * 64 + nt * 8 + lr;
                uint32_t b0 = Bs[(kb + lc) * 136 + n];
                uint32_t b1 = Bs[(kb + lc + 4) * 136 + n];
                mma8(acc[0][nt], a[0][0], a[0][1], a[0][2], a[0][3], b0, b1);
                mma8(acc[1][nt], a[1][0], a[1][1], a[1][2], a[1][3], b0, b1);
            }
        }
        __syncthreads();
    }

    // epilogue: C frag (lr, 2lc),(lr,2lc+1),(lr+8,2lc),(lr+8,2lc+1)
    #pragma unroll
    for (int mt = 0; mt < 2; ++mt) {
        #pragma unroll
        for (int nt = 0; nt < 8; ++nt) {
            int row = rowBase + wr * 32 + mt * 16 + lr;
            int col = colBase + wc * 64 + nt * 8 + 2 * lc;
            float b0 = bias[col], b1 = bias[col + 1];
            float2 o0, o1;
            o0.x = acc[mt][nt][0] + b0; o0.y = acc[mt][nt][1] + b1;
            o1.x = acc[mt][nt][2] + b0; o1.y = acc[mt][nt][3] + b1;
            if (SWISH) {
                o0.x = swishf(o0.x); o0.y = swishf(o0.y);
                o1.x = swishf(o1.x); o1.y = swishf(o1.y);
            }
            *(float2*)(C + (size_t)row * N + col) = o0;
            *(float2*)(C + (size_t)(row + 8) * N + col) = o1;
        }
    }
}

// =================================================================================
// Per-head projection: X[b,h,s,:] = q[b,s, h*128 : (h+1)*128] @ W_qkv[h]  (fp32)
// =================================================================================
__global__ __launch_bounds__(256)
void proj_kernel(const float* __restrict__ q, const float* __restrict__ Wqkv,
                 float* __restrict__ Xout)
{
    __shared__ float Ast[32][65];    // [k][row]
    __shared__ float Ws[32][128];    // [k][d]
    const int h = blockIdx.y;
    const int row0 = blockIdx.x * 64;
    const int tid = threadIdx.x;
    const int tx = tid & 15, ty = tid >> 4;
    const float* Wh = Wqkv + (size_t)h * HD * HD;

    float acc[4][8];
    #pragma unroll
    for (int m = 0; m < 4; ++m)
        #pragma unroll
        for (int n = 0; n < 8; ++n) acc[m][n] = 0.0f;

    for (int k0 = 0; k0 < HD; k0 += 32) {
        __syncthreads();
        for (int p = tid; p < 512; p += 256) {
            int r = p >> 3, k4 = (p & 7) << 2;
            float4 v = *(const float4*)(q + (size_t)(row0 + r) * DIMN + h * HD + k0 + k4);
            Ast[k4 + 0][r] = v.x; Ast[k4 + 1][r] = v.y;
            Ast[k4 + 2][r] = v.z; Ast[k4 + 3][r] = v.w;
        }
        for (int p = tid; p < 1024; p += 256) {
            int k = p >> 5, d4 = (p & 31) << 2;
            *(float4*)&Ws[k][d4] = *(const float4*)(Wh + (size_t)(k0 + k) * HD + d4);
        }
        __syncthreads();
        #pragma unroll
        for (int k = 0; k < 32; ++k) {
            float ra[4], rb[8];
            #pragma unroll
            for (int m = 0; m < 4; ++m) ra[m] = Ast[k][ty * 4 + m];
            #pragma unroll
            for (int n = 0; n < 8; ++n) rb[n] = Ws[k][tx + (n << 4)];
            #pragma unroll
            for (int m = 0; m < 4; ++m)
                #pragma unroll
                for (int n = 0; n < 8; ++n)
                    acc[m][n] = fmaf(ra[m], rb[n], acc[m][n]);
        }
    }
    #pragma unroll
    for (int m = 0; m < 4; ++m) {
        int i = row0 + ty * 4 + m;
        int b = i >> 11, s = i & (SEQ - 1);
        float* op = Xout + ((size_t)(b * NH + h) * SEQ + s) * HD;
        #pragma unroll
        for (int n = 0; n < 8; ++n) op[tx + (n << 4)] = acc[m][n];
    }
}

// =================================================================================
// Backward suffix scan: Sq[t] = X[t] + gamma * Sq[t+1]
// =================================================================================
__global__ void scan_kernel(float* __restrict__ Sq, const float* __restrict__ X)
{
    const int bh = blockIdx.x;
    const int h = bh & (NH - 1);
    const float gamma = 1.0f - exp2f(-5.0f - (float)h);
    const float* Xh = X + (size_t)bh * SEQ * HD;
    float* Sh = Sq + (size_t)bh * SEQ * HD;
    const int d = threadIdx.x;
    float sq = 0.0f;
    for (int t = SEQ - 1; t >= 0; --t) {
        sq = fmaf(gamma, sq, Xh[(size_t)t * HD + d]);
        Sh[(size_t)t * HD + d] = sq;
    }
}

// =================================================================================
// colscale
// =================================================================================
__global__ __launch_bounds__(256)
void colscale_kernel(float* __restrict__ colscale, const float* __restrict__ X,
                     const float* __restrict__ Sq)
{
    const int bh = blockIdx.x;
    const int h = bh & (NH - 1);
    const float gamma = 1.0f - exp2f(-5.0f - (float)h);
    const float l2g = log2f(gamma);
    const float inv1mg = exp2f(5.0f + (float)h);
    const int warp = threadIdx.x >> 5, lane = threadIdx.x & 31;
    const float inv_s = rsqrtf((float)HD);
    #pragma unroll
    for (int i = 0; i < 8; ++i) {
        int t = blockIdx.y * 64 + warp * 8 + i;
        const float* xr = X + ((size_t)bh * SEQ + t) * HD;
        const float* sr = Sq + ((size_t)bh * SEQ + t) * HD;
        float4 xv = *(const float4*)(xr + lane * 4);
        float4 sv = *(const float4*)(sr + lane * 4);
        float dot = xv.x * sv.x + xv.y * sv.y + xv.z * sv.z + xv.w * sv.w;
        #pragma unroll
        for (int o = 16; o; o >>= 1) dot += __shfl_xor_sync(0xffffffffu, dot, o);
        if (lane == 0) {
            float ct = (1.0f - exp2f((float)(SEQ - t) * l2g)) * inv1mg;
            float rs = rsqrtf(ct);
            float colsum = dot * rs * inv_s;
            colscale[(size_t)bh * SEQ + t] = rs * inv_s / fmaxf(fabsf(colsum), 1.0f);
        }
    }
}

// =================================================================================
// Retention via tf32 MMA: 64x64 q/k tiles, triangular key loop, K==V==X.
// Qs/KVs: [64][128] tf32, stride 136. Sw: [64][64] tf32 weighted scores, stride 72.
// 8 warps: wr=warp>>1 m16 tile rows wr*16; wc=warp&1: score cols wc*32, AV cols wc*64.
// =================================================================================
#define QS_STR  136
#define SW_STR  72
#define RET_U32 (64*QS_STR*2 + 64*SW_STR + 128)
#define RET_SMEM (RET_U32 * 4)

__global__ __launch_bounds__(256)
void retention_tf32(float* __restrict__ out, const float* __restrict__ X,
                    const float* __restrict__ colscale)
{
    extern __shared__ uint32_t sm[];
    uint32_t* Qs  = sm;                        // 64 x 136
    uint32_t* KVs = Qs + 64 * QS_STR;          // 64 x 136
    uint32_t* Sw  = KVs + 64 * QS_STR;         // 64 x 72
    float* wcol = (float*)(Sw + 64 * SW_STR);  // 64
    float* powr = wcol + 64;                   // 64

    const int sb = blockIdx.x;
    const int bh = blockIdx.y;
    const int h = bh & (NH - 1);
    const int b = bh >> 3;
    const float gamma = 1.0f - exp2f(-5.0f - (float)h);
    const float l2g = log2f(gamma);
    const float* Xh = X + (size_t)bh * SEQ * HD;
    const float* csb = colscale + (size_t)bh * SEQ;
    const int tid = threadIdx.x;
    const int warp = tid >> 5, lane = tid & 31;
    const int wr = warp >> 1, wc = warp & 1;
    const int lr = lane >> 2, lc = lane & 3;
    const int s0 = sb * 64;
    const int mrow = wr * 16;   // warp's m16 tile base row

    // Q tile (tf32)
    #pragma unroll
    for (int q4 = 0; q4 < 2; ++q4) {
        int p = tid + q4 * 256;
        int r = p >> 3, kc = (p & 7) << 4;   // 64 rows x 2 chunks of 16
        #pragma unroll
        for (int c = 0; c < 4; ++c) {
            float4 v = *(const float4*)(Xh + (size_t)(s0 + r) * HD + kc + c * 4);
            uint32_t* dst = &Qs[r * QS_STR + kc + c * 4];
            dst[0] = f2tf32(v.x); dst[1] = f2tf32(v.y);
            dst[2] = f2tf32(v.z); dst[3] = f2tf32(v.w);
        }
    }
    if (tid < 64) powr[tid] = exp2f((float)tid * l2g);

    float accO[8][4];
    #pragma unroll
    for (int nt = 0; nt < 8; ++nt)
        #pragma unroll
        for (int i = 0; i < 4; ++i) accO[nt][i] = 0.0f;

    for (int jb = 0; jb <= sb; ++jb) {
        const int t0 = jb * 64;
        __syncthreads();   // previous iteration's KVs/Sw readers done
        // KV tile (tf32)
        #pragma unroll
        for (int q4 = 0; q4 < 2; ++q4) {
            int p = tid + q4 * 256;
            int r = p >> 3, kc = (p & 7) << 4;
            #pragma unroll
            for (int c = 0; c < 4; ++c) {
                float4 v = *(const float4*)(Xh + (size_t)(t0 + r) * HD + kc + c * 4);
                uint32_t* dst = &KVs[r * QS_STR + kc + c * 4];
                dst[0] = f2tf32(v.x); dst[1] = f2tf32(v.y);
                dst[2] = f2tf32(v.z); dst[3] = f2tf32(v.w);
            }
        }
        if (tid < 64)
            wcol[tid] = exp2f((float)(s0 - t0 - tid) * l2g) * csb[t0 + tid];
        __syncthreads();

        // ---- scores: S = Q @ K^T  (B[k][n] = K[n][k] -> KVs[n*str + k]) ----
        float accS[4][4];
        #pragma unroll
        for (int nt = 0; nt < 4; ++nt)
            #pragma unroll
            for (int i = 0; i < 4; ++i) accS[nt][i] = 0.0f;
        #pragma unroll
        for (int k8 = 0; k8 < 16; ++k8) {
            const int kb = k8 * 8;
            uint32_t a0 = Qs[(mrow + lr) * QS_STR + kb + lc];
            uint32_t a1 = Qs[(mrow + lr + 8) * QS_STR + kb + lc];
            uint32_t a2 = Qs[(mrow + lr) * QS_STR + kb + lc + 4];
            uint32_t a3 = Qs[(mrow + lr + 8) * QS_STR + kb + lc + 4];
            #pragma unroll
            for (int nt = 0; nt < 4; ++nt) {
                int n = wc * 32 + nt * 8 + lr;
                uint32_t b0 = KVs[n * QS_STR + kb + lc];
                uint32_t b1 = KVs[n * QS_STR + kb + lc + 4];
                mma8(accS[nt], a0, a1, a2, a3, b0, b1);
            }
        }
        // weight + stage to Sw (tf32)
        #pragma unroll
        for (int nt = 0; nt < 4; ++nt) {
            #pragma unroll
            for (int half = 0; half < 2; ++half) {
                int rl = mrow + lr + half * 8;
                int srow = s0 + rl;
                float pr = powr[rl];
                #pragma unroll
                for (int e = 0; e < 2; ++e) {
                    int cl = wc * 32 + nt * 8 + 2 * lc + e;
                    float w = (srow >= t0 + cl) ? pr * wcol[cl] : 0.0f;
                    Sw[rl * SW_STR + cl] = f2tf32(accS[nt][half * 2 + e] * w);
                }
            }
        }
        __syncthreads();

        // ---- accO += Sw @ KV  (B[k][n] = KVs[k*str + n]) ----
        #pragma unroll
        for (int k8 = 0; k8 < 8; ++k8) {
            const int kb = k8 * 8;
            uint32_t a0 = Sw[(mrow + lr) * SW_STR + kb + lc];
            uint32_t a1 = Sw[(mrow + lr + 8) * SW_STR + kb + lc];
            uint32_t a2 = Sw[(mrow + lr) * SW_STR + kb + lc + 4];
            uint32_t a3 = Sw[(mrow + lr + 8) * SW_STR + kb + lc + 4];
            #pragma unroll
            for (int nt = 0; nt < 8; ++nt) {
                int n = wc * 64 + nt * 8 + lr;
                uint32_t b0 = KVs[(kb + lc) * QS_STR + n];
                uint32_t b1 = KVs[(kb + lc + 4) * QS_STR + n];
                mma8(accO[nt], a0, a1, a2, a3, b0, b1);
            }
        }
    }

    // epilogue
    #pragma unroll
    for (int nt = 0; nt < 8; ++nt) {
        int srow = s0 + mrow + lr;
        int d = wc * 64 + nt * 8 + 2 * lc;
        float* op0 = out + ((size_t)(b * SEQ + srow)) * DIMN + h * HD + d;
        float* op1 = out + ((size_t)(b * SEQ + srow + 8)) * DIMN + h * HD + d;
        *(float2*)op0 = make_float2(accO[nt][0], accO[nt][1]);
        *(float2*)op1 = make_float2(accO[nt][2], accO[nt][3]);
    }
}

// =================================================================================
// GroupNorm: 32 groups of 32 channels, population var, eps=1e-3, + beta
// =================================================================================
__global__ __launch_bounds__(256)
void groupnorm_kernel(float* __restrict__ Y, const float* __restrict__ Xin,
                      const float* __restrict__ beta)
{
    int row = blockIdx.x >> 2;
    int gblk = blockIdx.x & 3;
    int warp = threadIdx.x >> 5, lane = threadIdx.x & 31;
    int c = gblk * 256 + warp * 32 + lane;
    float x = Xin[(size_t)row * DIMN + c];
    float s = x, s2 = x * x;
    #pragma unroll
    for (int o = 16; o; o >>= 1) {
        s  += __shfl_xor_sync(0xffffffffu, s, o);
        s2 += __shfl_xor_sync(0xffffffffu, s2, o);
    }
    float mu = s * (1.0f / 32.0f);
    float var = s2 * (1.0f / 32.0f) - mu * mu;
    float y = (x - mu) * rsqrtf(var + 1e-3f) + beta[c];
    Y[(size_t)row * DIMN + c] = y;
}

// =================================================================================
// Launch
// =================================================================================
extern "C" void kernel_launch(void* const* d_in, const int* in_sizes, int n_in,
                              void* d_out, int out_size)
{
    const float* q    = (const float*)d_in[0];
    // d_in[1] = k, d_in[2] = v : unused by the reference (retention uses q for Q,K,V)
    const float* Wqkv = (const float*)d_in[3];
    const float* Wg   = (const float*)d_in[4];
    const float* bg   = (const float*)d_in[5];
    const float* Wo   = (const float*)d_in[6];
    const float* bo   = (const float*)d_in[7];
    const float* beta = (const float*)d_in[8];
    float* out = (float*)d_out;

    float *wgate, *xy, *sr, *cscale;
    cudaGetSymbolAddress((void**)&wgate, g_wgate);
    cudaGetSymbolAddress((void**)&xy, g_xy);
    cudaGetSymbolAddress((void**)&sr, g_sr);
    cudaGetSymbolAddress((void**)&cscale, g_colscale);

    cudaFuncSetAttribute(retention_tf32, cudaFuncAttributeMaxDynamicSharedMemorySize, RET_SMEM);

    // 1. Wgate = swish(q @ Wg + bg)
    sgemm_tf32<true, false><<<dim3(DIMN / 128, MROWS / 128), 256>>>(q, nullptr, Wg, bg, wgate, DIMN, DIMN);
    // 2. X[b,h,s,:] = q_h @ W_qkv[h]
    proj_kernel<<<dim3(MROWS / 64, NH), 256>>>(q, Wqkv, xy);
    // 3. Sq suffix scan (into g_sr)
    scan_kernel<<<BATCH * NH, HD>>>(sr, xy);
    // 4. per-column scale
    colscale_kernel<<<dim3(BATCH * NH, SEQ / 64), 256>>>(cscale, xy, sr);
    // 5. retention (overwrites g_sr with attention output, interleaved [row, h*128+d])
    retention_tf32<<<dim3(SEQ / 64, BATCH * NH), 256, RET_SMEM>>>(sr, xy, cscale);
    // 6. group norm (writes Y into g_xy)
    groupnorm_kernel<<<MROWS * 4, 256>>>(xy, sr, beta);
    // 7. out = (Wgate ⊙ Y) @ Wo + bo
    sgemm_tf32<false, true><<<dim3(DIMN / 128, MROWS / 128), 256>>>(wgate, xy, Wo, bo, out, DIMN, DIMN);
}

// round 11
// speedup vs baseline: 2.9198x; 1.2345x over previous
#include <cuda_runtime.h>
#include <math.h>
#include <stdint.h>

#define BATCH 4
#define SEQ   2048
#define DIMN  1024
#define NH    8
#define HD    128
#define MROWS (BATCH*SEQ)   // 8192

// ---------------- scratch (device globals; no runtime allocation) ----------------
__device__ float g_wgate[(size_t)MROWS*DIMN];          // Wgate
__device__ float g_xy[(size_t)MROWS*DIMN];             // X (per-head proj) then Y (groupnorm out)
__device__ float g_sr[(size_t)MROWS*DIMN];             // Sq (suffix scan) then retention out
__device__ float g_colscale[(size_t)BATCH*NH*SEQ];     // per-column scale

__device__ __forceinline__ float swishf(float x) { return x / (1.0f + expf(-x)); }

__device__ __forceinline__ uint32_t f2tf32(float x) {
    uint32_t y;
    asm("cvt.rna.tf32.f32 %0, %1;" : "=r"(y) : "f"(x));
    return y;
}

// D += A*B, m16n8k8 tf32, fp32 accumulate
__device__ __forceinline__ void mma8(float* d, uint32_t a0, uint32_t a1, uint32_t a2, uint32_t a3,
                                     uint32_t b0, uint32_t b1) {
    asm volatile("mma.sync.aligned.m16n8k8.row.col.f32.tf32.tf32.f32 "
                 "{%0,%1,%2,%3},{%4,%5,%6,%7},{%8,%9},{%0,%1,%2,%3};"
                 : "+f"(d[0]), "+f"(d[1]), "+f"(d[2]), "+f"(d[3])
                 : "r"(a0), "r"(a1), "r"(a2), "r"(a3), "r"(b0), "r"(b1));
}

// =================================================================================
// TF32 tensor-core SGEMM with software-pipelined global loads.
// C = epi(A (⊙A2) @ B + bias). 128x128 block, 8 warps, warp tile 32x64.
// =================================================================================
template<bool SWISH, bool AMUL>
__global__ __launch_bounds__(256)
void sgemm_tf32(const float* __restrict__ A, const float* __restrict__ A2,
                const float* __restrict__ Bm, const float* __restrict__ bias,
                float* __restrict__ C, int K, int N)
{
    __shared__ uint32_t As[128 * 36];
    __shared__ uint32_t Bs[32 * 136];
    const int tid = threadIdx.x;
    const int warp = tid >> 5, lane = tid & 31;
    const int wr = warp >> 1, wc = warp & 1;
    const int lr = lane >> 2, lc = lane & 3;
    const int rowBase = blockIdx.y * 128;
    const int colBase = blockIdx.x * 128;

    // per-thread load coords
    const int aR = tid >> 3, aC = (tid & 7) << 2;     // + q4*32 rows
    const int bR = tid >> 6, bC = (tid & 63) << 1;    // 32x128 via 4 q4: r = bR + q4*4? (see below)

    float acc[2][8][4];
    #pragma unroll
    for (int mt = 0; mt < 2; ++mt)
        #pragma unroll
        for (int nt = 0; nt < 8; ++nt)
            #pragma unroll
            for (int i = 0; i < 4; ++i) acc[mt][nt][i] = 0.0f;

    float4 ra[4], rb[4];

    auto loadTiles = [&](int k0) {
        #pragma unroll
        for (int q4 = 0; q4 < 4; ++q4) {
            int r = aR + q4 * 32;
            float4 v = *(const float4*)(A + (size_t)(rowBase + r) * K + k0 + aC);
            if (AMUL) {
                float4 w = *(const float4*)(A2 + (size_t)(rowBase + r) * K + k0 + aC);
                v.x *= w.x; v.y *= w.y; v.z *= w.z; v.w *= w.w;
            }
            ra[q4] = v;
        }
        #pragma unroll
        for (int q4 = 0; q4 < 4; ++q4) {
            int p = tid + q4 * 256;
            int r = p >> 5, nc = (p & 31) << 2;
            rb[q4] = *(const float4*)(Bm + (size_t)(k0 + r) * N + colBase + nc);
        }
    };
    auto stsTiles = [&]() {
        #pragma unroll
        for (int q4 = 0; q4 < 4; ++q4) {
            int r = aR + q4 * 32;
            uint32_t* dst = &As[r * 36 + aC];
            dst[0] = f2tf32(ra[q4].x); dst[1] = f2tf32(ra[q4].y);
            dst[2] = f2tf32(ra[q4].z); dst[3] = f2tf32(ra[q4].w);
        }
        #pragma unroll
        for (int q4 = 0; q4 < 4; ++q4) {
            int p = tid + q4 * 256;
            int r = p >> 5, nc = (p & 31) << 2;
            uint32_t* dst = &Bs[r * 136 + nc];
            dst[0] = f2tf32(rb[q4].x); dst[1] = f2tf32(rb[q4].y);
            dst[2] = f2tf32(rb[q4].z); dst[3] = f2tf32(rb[q4].w);
        }
    };

    loadTiles(0);
    stsTiles();
    __syncthreads();

    for (int k0 = 0; k0 < K; k0 += 32) {
        const bool hasNext = (k0 + 32) < K;
        if (hasNext) loadTiles(k0 + 32);     // LDG overlapped with MMA below
        #pragma unroll
        for (int k8 = 0; k8 < 4; ++k8) {
            const int kb = k8 * 8;
            uint32_t a[2][4];
            #pragma unroll
            for (int mt = 0; mt < 2; ++mt) {
                int m = wr * 32 + mt * 16;
                a[mt][0] = As[(m + lr) * 36 + kb + lc];
                a[mt][1] = As[(m + lr + 8) * 36 + kb + lc];
                a[mt][2] = As[(m + lr) * 36 + kb + lc + 4];
                a[mt][3] = As[(m + lr + 8) * 36 + kb + lc + 4];
            }
            #pragma unroll
            for (int nt = 0; nt < 8; ++nt) {
                int n = wc * 64 + nt * 8 + lr;
                uint32_t b0 = Bs[(kb + lc) * 136 + n];
                uint32_t b1 = Bs[(kb + lc + 4) * 136 + n];
                mma8(acc[0][nt], a[0][0], a[0][1], a[0][2], a[0][3], b0, b1);
                mma8(acc[1][nt], a[1][0], a[1][1], a[1][2], a[1][3], b0, b1);
            }
        }
        __syncthreads();
        if (hasNext) {
            stsTiles();
            __syncthreads();
        }
    }

    #pragma unroll
    for (int mt = 0; mt < 2; ++mt) {
        #pragma unroll
        for (int nt = 0; nt < 8; ++nt) {
            int row = rowBase + wr * 32 + mt * 16 + lr;
            int col = colBase + wc * 64 + nt * 8 + 2 * lc;
            float b0 = bias[col], b1 = bias[col + 1];
            float2 o0, o1;
            o0.x = acc[mt][nt][0] + b0; o0.y = acc[mt][nt][1] + b1;
            o1.x = acc[mt][nt][2] + b0; o1.y = acc[mt][nt][3] + b1;
            if (SWISH) {
                o0.x = swishf(o0.x); o0.y = swishf(o0.y);
                o1.x = swishf(o1.x); o1.y = swishf(o1.y);
            }
            *(float2*)(C + (size_t)row * N + col) = o0;
            *(float2*)(C + (size_t)(row + 8) * N + col) = o1;
        }
    }
}

// =================================================================================
// Per-head projection via tf32 MMA: X[b,h,s,:] = q[b,s, h*128:(h+1)*128] @ W_qkv[h]
// 128 rows x 128 cols per block, grid (MROWS/128, NH). K = 128.
// =================================================================================
__global__ __launch_bounds__(256)
void proj_tf32(const float* __restrict__ q, const float* __restrict__ Wqkv,
               float* __restrict__ Xout)
{
    __shared__ uint32_t As[128 * 36];
    __shared__ uint32_t Bs[32 * 136];
    const int tid = threadIdx.x;
    const int warp = tid >> 5, lane = tid & 31;
    const int wr = warp >> 1, wc = warp & 1;
    const int lr = lane >> 2, lc = lane & 3;
    const int rowBase = blockIdx.x * 128;
    const int h = blockIdx.y;
    const float* Wh = Wqkv + (size_t)h * HD * HD;
    const int aR = tid >> 3, aC = (tid & 7) << 2;

    float acc[2][8][4];
    #pragma unroll
    for (int mt = 0; mt < 2; ++mt)
        #pragma unroll
        for (int nt = 0; nt < 8; ++nt)
            #pragma unroll
            for (int i = 0; i < 4; ++i) acc[mt][nt][i] = 0.0f;

    float4 ra[4], rb[4];
    auto loadTiles = [&](int k0) {
        #pragma unroll
        for (int q4 = 0; q4 < 4; ++q4) {
            int r = aR + q4 * 32;
            ra[q4] = *(const float4*)(q + (size_t)(rowBase + r) * DIMN + h * HD + k0 + aC);
        }
        #pragma unroll
        for (int q4 = 0; q4 < 4; ++q4) {
            int p = tid + q4 * 256;
            int r = p >> 5, nc = (p & 31) << 2;
            rb[q4] = *(const float4*)(Wh + (size_t)(k0 + r) * HD + nc);
        }
    };
    auto stsTiles = [&]() {
        #pragma unroll
        for (int q4 = 0; q4 < 4; ++q4) {
            int r = aR + q4 * 32;
            uint32_t* dst = &As[r * 36 + aC];
            dst[0] = f2tf32(ra[q4].x); dst[1] = f2tf32(ra[q4].y);
            dst[2] = f2tf32(ra[q4].z); dst[3] = f2tf32(ra[q4].w);
        }
        #pragma unroll
        for (int q4 = 0; q4 < 4; ++q4) {
            int p = tid + q4 * 256;
            int r = p >> 5, nc = (p & 31) << 2;
            uint32_t* dst = &Bs[r * 136 + nc];
            dst[0] = f2tf32(rb[q4].x); dst[1] = f2tf32(rb[q4].y);
            dst[2] = f2tf32(rb[q4].z); dst[3] = f2tf32(rb[q4].w);
        }
    };

    loadTiles(0);
    stsTiles();
    __syncthreads();

    for (int k0 = 0; k0 < HD; k0 += 32) {
        const bool hasNext = (k0 + 32) < HD;
        if (hasNext) loadTiles(k0 + 32);
        #pragma unroll
        for (int k8 = 0; k8 < 4; ++k8) {
            const int kb = k8 * 8;
            uint32_t a[2][4];
            #pragma unroll
            for (int mt = 0; mt < 2; ++mt) {
                int m = wr * 32 + mt * 16;
                a[mt][0] = As[(m + lr) * 36 + kb + lc];
                a[mt][1] = As[(m + lr + 8) * 36 + kb + lc];
                a[mt][2] = As[(m + lr) * 36 + kb + lc + 4];
                a[mt][3] = As[(m + lr + 8) * 36 + kb + lc + 4];
            }
            #pragma unroll
            for (int nt = 0; nt < 8; ++nt) {
                int n = wc * 64 + nt * 8 + lr;
                uint32_t b0 = Bs[(kb + lc) * 136 + n];
                uint32_t b1 = Bs[(kb + lc + 4) * 136 + n];
                mma8(acc[0][nt], a[0][0], a[0][1], a[0][2], a[0][3], b0, b1);
                mma8(acc[1][nt], a[1][0], a[1][1], a[1][2], a[1][3], b0, b1);
            }
        }
        __syncthreads();
        if (hasNext) {
            stsTiles();
            __syncthreads();
        }
    }

    #pragma unroll
    for (int mt = 0; mt < 2; ++mt) {
        #pragma unroll
        for (int nt = 0; nt < 8; ++nt) {
            int i0 = rowBase + wr * 32 + mt * 16 + lr;
            int col = wc * 64 + nt * 8 + 2 * lc;
            #pragma unroll
            for (int half = 0; half < 2; ++half) {
                int i = i0 + half * 8;
                int b = i >> 11, s = i & (SEQ - 1);
                float* op = Xout + ((size_t)(b * NH + h) * SEQ + s) * HD + col;
                *(float2*)op = make_float2(acc[mt][nt][half * 2], acc[mt][nt][half * 2 + 1]);
            }
        }
    }
}

// =================================================================================
// Backward suffix scan: Sq[t] = X[t] + gamma * Sq[t+1].
// grid (BH, 4 d-slices), block 32 -> 128 blocks spread across SMs for bandwidth.
// =================================================================================
__global__ void scan_kernel(float* __restrict__ Sq, const float* __restrict__ X)
{
    const int bh = blockIdx.x;
    const int h = bh & (NH - 1);
    const float gamma = 1.0f - exp2f(-5.0f - (float)h);
    const int d = blockIdx.y * 32 + threadIdx.x;
    const float* Xh = X + (size_t)bh * SEQ * HD;
    float* Sh = Sq + (size_t)bh * SEQ * HD;
    float sq = 0.0f;
    for (int t = SEQ - 1; t >= 0; --t) {
        sq = fmaf(gamma, sq, Xh[(size_t)t * HD + d]);
        Sh[(size_t)t * HD + d] = sq;
    }
}

// =================================================================================
// colscale
// =================================================================================
__global__ __launch_bounds__(256)
void colscale_kernel(float* __restrict__ colscale, const float* __restrict__ X,
                     const float* __restrict__ Sq)
{
    const int bh = blockIdx.x;
    const int h = bh & (NH - 1);
    const float gamma = 1.0f - exp2f(-5.0f - (float)h);
    const float l2g = log2f(gamma);
    const float inv1mg = exp2f(5.0f + (float)h);
    const int warp = threadIdx.x >> 5, lane = threadIdx.x & 31;
    const float inv_s = rsqrtf((float)HD);
    #pragma unroll
    for (int i = 0; i < 8; ++i) {
        int t = blockIdx.y * 64 + warp * 8 + i;
        const float* xr = X + ((size_t)bh * SEQ + t) * HD;
        const float* sr = Sq + ((size_t)bh * SEQ + t) * HD;
        float4 xv = *(const float4*)(xr + lane * 4);
        float4 sv = *(const float4*)(sr + lane * 4);
        float dot = xv.x * sv.x + xv.y * sv.y + xv.z * sv.z + xv.w * sv.w;
        #pragma unroll
        for (int o = 16; o; o >>= 1) dot += __shfl_xor_sync(0xffffffffu, dot, o);
        if (lane == 0) {
            float ct = (1.0f - exp2f((float)(SEQ - t) * l2g)) * inv1mg;
            float rs = rsqrtf(ct);
            float colsum = dot * rs * inv_s;
            colscale[(size_t)bh * SEQ + t] = rs * inv_s / fmaxf(fabsf(colsum), 1.0f);
        }
    }
}

// =================================================================================
// Retention v2: 128(q) x 64(k) tiles, tf32 MMA, K==V==X.
// Row decay gamma^(s-s0) applied in epilogue (exact factorization).
// Next KV tile LDG issued before the AV matmul (latency hidden).
// Warps: wm = warp&3 -> rows wm*32 (2 m16 tiles); wn = warp>>2 -> score keys wn*32,
// AV d-cols wn*64.
// =================================================================================
#define QTILE  128
#define KTILE  64
#define QS_STR 136
#define SW_STR 68
#define RET_U32 (QTILE*QS_STR + KTILE*QS_STR + QTILE*SW_STR + KTILE + QTILE)
#define RET_SMEM (RET_U32 * 4)

__global__ __launch_bounds__(256, 1)
void retention_tf32(float* __restrict__ out, const float* __restrict__ X,
                    const float* __restrict__ colscale)
{
    extern __shared__ uint32_t sm[];
    uint32_t* Qs  = sm;                          // 128 x 136
    uint32_t* KVs = Qs + QTILE * QS_STR;         // 64 x 136
    uint32_t* Sw  = KVs + KTILE * QS_STR;        // 128 x 68
    float* wcol = (float*)(Sw + QTILE * SW_STR); // 64
    float* powr = wcol + KTILE;                  // 128

    const int sb = (int)gridDim.x - 1 - (int)blockIdx.x;   // longest blocks first
    const int bh = blockIdx.y;
    const int h = bh & (NH - 1);
    const int b = bh >> 3;
    const float gamma = 1.0f - exp2f(-5.0f - (float)h);
    const float l2g = log2f(gamma);
    const float* Xh = X + (size_t)bh * SEQ * HD;
    const float* csb = colscale + (size_t)bh * SEQ;
    const int tid = threadIdx.x;
    const int warp = tid >> 5, lane = tid & 31;
    const int wm = warp & 3, wn = warp >> 2;
    const int lr = lane >> 2, lc = lane & 3;
    const int s0 = sb * QTILE;
    const int mbase = wm * 32;
    const int jbmax = 2 * sb + 1;

    // Q tile (128x128 -> tf32)
    #pragma unroll
    for (int i = 0; i < 16; ++i) {
        int p = tid + i * 256;
        int r = p >> 5, c4 = (p & 31) << 2;
        float4 v = *(const float4*)(Xh + (size_t)(s0 + r) * HD + c4);
        uint32_t* dst = &Qs[r * QS_STR + c4];
        dst[0] = f2tf32(v.x); dst[1] = f2tf32(v.y);
        dst[2] = f2tf32(v.z); dst[3] = f2tf32(v.w);
    }
    if (tid < QTILE) powr[tid] = exp2f((float)tid * l2g);
    // KV tile 0 + wcol 0
    {
        #pragma unroll
        for (int i = 0; i < 8; ++i) {
            int p = tid + i * 256;
            int r = p >> 5, c4 = (p & 31) << 2;
            float4 v = *(const float4*)(Xh + (size_t)r * HD + c4);
            uint32_t* dst = &KVs[r * QS_STR + c4];
            dst[0] = f2tf32(v.x); dst[1] = f2tf32(v.y);
            dst[2] = f2tf32(v.z); dst[3] = f2tf32(v.w);
        }
        if (tid < KTILE) wcol[tid] = exp2f((float)(s0 - tid) * l2g) * csb[tid];
    }
    __syncthreads();

    float accO[2][8][4];
    #pragma unroll
    for (int mt = 0; mt < 2; ++mt)
        #pragma unroll
        for (int nt = 0; nt < 8; ++nt)
            #pragma unroll
            for (int i = 0; i < 4; ++i) accO[mt][nt][i] = 0.0f;

    for (int jb = 0; jb <= jbmax; ++jb) {
        const int t0 = jb * KTILE;
        const bool maskNeeded = (jb >= 2 * sb);
        const bool active = (s0 + mbase + 31 >= t0);

        if (active) {
            // ---- scores: S = Q @ K^T ----
            float accS[2][4][4];
            #pragma unroll
            for (int mt = 0; mt < 2; ++mt)
                #pragma unroll
                for (int nt = 0; nt < 4; ++nt)
                    #pragma unroll
                    for (int i = 0; i < 4; ++i) accS[mt][nt][i] = 0.0f;
            #pragma unroll
            for (int k8 = 0; k8 < 16; ++k8) {
                const int kb = k8 * 8;
                uint32_t a[2][4];
                #pragma unroll
                for (int mt = 0; mt < 2; ++mt) {
                    int m = mbase + mt * 16;
                    a[mt][0] = Qs[(m + lr) * QS_STR + kb + lc];
                    a[mt][1] = Qs[(m + lr + 8) * QS_STR + kb + lc];
                    a[mt][2] = Qs[(m + lr) * QS_STR + kb + lc + 4];
                    a[mt][3] = Qs[(m + lr + 8) * QS_STR + kb + lc + 4];
                }
                #pragma unroll
                for (int nt = 0; nt < 4; ++nt) {
                    int n = wn * 32 + nt * 8 + lr;
                    uint32_t b0 = KVs[n * QS_STR + kb + lc];
                    uint32_t b1 = KVs[n * QS_STR + kb + lc + 4];
                    mma8(accS[0][nt], a[0][0], a[0][1], a[0][2], a[0][3], b0, b1);
                    mma8(accS[1][nt], a[1][0], a[1][1], a[1][2], a[1][3], b0, b1);
                }
            }
            // stage weighted scores (column factor only; row factor in epilogue)
            #pragma unroll
            for (int mt = 0; mt < 2; ++mt) {
                #pragma unroll
                for (int nt = 0; nt < 4; ++nt) {
                    #pragma unroll
                    for (int half = 0; half < 2; ++half) {
                        int rl = mbase + mt * 16 + lr + half * 8;
                        #pragma unroll
                        for (int e = 0; e < 2; ++e) {
                            int cl = wn * 32 + nt * 8 + 2 * lc + e;
                            float w = wcol[cl];
                            if (maskNeeded && (s0 + rl < t0 + cl)) w = 0.0f;
                            Sw[rl * SW_STR + cl] = f2tf32(accS[mt][nt][half * 2 + e] * w);
                        }
                    }
                }
            }
        }
        __syncthreads();   // Sw visible cross-warp (AV reads full 64-key columns)

        // early global load of next KV tile (hidden under AV)
        const bool hasNext = (jb < jbmax);
        float4 nv[8];
        if (hasNext) {
            const int t0n = t0 + KTILE;
            #pragma unroll
            for (int i = 0; i < 8; ++i) {
                int p = tid + i * 256;
                int r = p >> 5, c4 = (p & 31) << 2;
                nv[i] = *(const float4*)(Xh + (size_t)(t0n + r) * HD + c4);
            }
        }

        if (active) {
            // ---- accO += Sw @ KV ----
            #pragma unroll
            for (int k8 = 0; k8 < 8; ++k8) {
                const int kb = k8 * 8;
                uint32_t a[2][4];
                #pragma unroll
                for (int mt = 0; mt < 2; ++mt) {
                    int m = mbase + mt * 16;
                    a[mt][0] = Sw[(m + lr) * SW_STR + kb + lc];
                    a[mt][1] = Sw[(m + lr + 8) * SW_STR + kb + lc];
                    a[mt][2] = Sw[(m + lr) * SW_STR + kb + lc + 4];
                    a[mt][3] = Sw[(m + lr + 8) * SW_STR + kb + lc + 4];
                }
                #pragma unroll
                for (int nt = 0; nt < 8; ++nt) {
                    int n = wn * 64 + nt * 8 + lr;
                    uint32_t b0 = KVs[(kb + lc) * QS_STR + n];
                    uint32_t b1 = KVs[(kb + lc + 4) * QS_STR + n];
                    mma8(accO[0][nt], a[0][0], a[0][1], a[0][2], a[0][3], b0, b1);
                    mma8(accO[1][nt], a[1][0], a[1][1], a[1][2], a[1][3], b0, b1);
                }
            }
        }
        __syncthreads();   // everyone done reading KVs / wcol
        if (hasNext) {
            #pragma unroll
            for (int i = 0; i < 8; ++i) {
                int p = tid + i * 256;
                int r = p >> 5, c4 = (p & 31) << 2;
                uint32_t* dst = &KVs[r * QS_STR + c4];
                dst[0] = f2tf32(nv[i].x); dst[1] = f2tf32(nv[i].y);
                dst[2] = f2tf32(nv[i].z); dst[3] = f2tf32(nv[i].w);
            }
            if (tid < KTILE) {
                int t0n = t0 + KTILE;
                wcol[tid] = exp2f((float)(s0 - t0n - tid) * l2g) * csb[t0n + tid];
            }
        }
        __syncthreads();   // new KV/wcol visible for next iteration's score phase
    }

    // epilogue: apply row decay gamma^(s - s0)
    #pragma unroll
    for (int mt = 0; mt < 2; ++mt) {
        int rl = mbase + mt * 16 + lr;
        float p0 = powr[rl], p1 = powr[rl + 8];
        int srow = s0 + rl;
        #pragma unroll
        for (int nt = 0; nt < 8; ++nt) {
            int d = wn * 64 + nt * 8 + 2 * lc;
            float* op0 = out + ((size_t)(b * SEQ + srow)) * DIMN + h * HD + d;
            float* op1 = out + ((size_t)(b * SEQ + srow + 8)) * DIMN + h * HD + d;
            *(float2*)op0 = make_float2(accO[mt][nt][0] * p0, accO[mt][nt][1] * p0);
            *(float2*)op1 = make_float2(accO[mt][nt][2] * p1, accO[mt][nt][3] * p1);
        }
    }
}

// =================================================================================
// GroupNorm: 32 groups of 32 channels, population var, eps=1e-3, + beta
// =================================================================================
__global__ __launch_bounds__(256)
void groupnorm_kernel(float* __restrict__ Y, const float* __restrict__ Xin,
                      const float* __restrict__ beta)
{
    int row = blockIdx.x >> 2;
    int gblk = blockIdx.x & 3;
    int warp = threadIdx.x >> 5, lane = threadIdx.x & 31;
    int c = gblk * 256 + warp * 32 + lane;
    float x = Xin[(size_t)row * DIMN + c];
    float s = x, s2 = x * x;
    #pragma unroll
    for (int o = 16; o; o >>= 1) {
        s  += __shfl_xor_sync(0xffffffffu, s, o);
        s2 += __shfl_xor_sync(0xffffffffu, s2, o);
    }
    float mu = s * (1.0f / 32.0f);
    float var = s2 * (1.0f / 32.0f) - mu * mu;
    float y = (x - mu) * rsqrtf(var + 1e-3f) + beta[c];
    Y[(size_t)row * DIMN + c] = y;
}

// =================================================================================
// Launch
// =================================================================================
extern "C" void kernel_launch(void* const* d_in, const int* in_sizes, int n_in,
                              void* d_out, int out_size)
{
    const float* q    = (const float*)d_in[0];
    // d_in[1] = k, d_in[2] = v : unused by the reference (retention uses q for Q,K,V)
    const float* Wqkv = (const float*)d_in[3];
    const float* Wg   = (const float*)d_in[4];
    const float* bg   = (const float*)d_in[5];
    const float* Wo   = (const float*)d_in[6];
    const float* bo   = (const float*)d_in[7];
    const float* beta = (const float*)d_in[8];
    float* out = (float*)d_out;

    float *wgate, *xy, *sr, *cscale;
    cudaGetSymbolAddress((void**)&wgate, g_wgate);
    cudaGetSymbolAddress((void**)&xy, g_xy);
    cudaGetSymbolAddress((void**)&sr, g_sr);
    cudaGetSymbolAddress((void**)&cscale, g_colscale);

    cudaFuncSetAttribute(retention_tf32, cudaFuncAttributeMaxDynamicSharedMemorySize, RET_SMEM);

    // 1. Wgate = swish(q @ Wg + bg)
    sgemm_tf32<true, false><<<dim3(DIMN / 128, MROWS / 128), 256>>>(q, nullptr, Wg, bg, wgate, DIMN, DIMN);
    // 2. X[b,h,s,:] = q_h @ W_qkv[h]
    proj_tf32<<<dim3(MROWS / 128, NH), 256>>>(q, Wqkv, xy);
    // 3. Sq suffix scan (into g_sr)
    scan_kernel<<<dim3(BATCH * NH, 4), 32>>>(sr, xy);
    // 4. per-column scale
    colscale_kernel<<<dim3(BATCH * NH, SEQ / 64), 256>>>(cscale, xy, sr);
    // 5. retention (overwrites g_sr with attention output, interleaved [row, h*128+d])
    retention_tf32<<<dim3(SEQ / QTILE, BATCH * NH), 256, RET_SMEM>>>(sr, xy, cscale);
    // 6. group norm (writes Y into g_xy)
    groupnorm_kernel<<<MROWS * 4, 256>>>(xy, sr, beta);
    // 7. out = (Wgate ⊙ Y) @ Wo + bo
    sgemm_tf32<false, true><<<dim3(DIMN / 128, MROWS / 128), 256>>>(wgate, xy, Wo, bo, out, DIMN, DIMN);
}